// round 8
// baseline (speedup 1.0000x reference)
#include <cuda_runtime.h>
#include <cuda_fp16.h>
#include <cstdint>

// ---------------- problem constants ----------------
#define NNODES 50000
#define DHEAD  64
#define HIDN   256
#define KDIM   512
#define TILE_E 64            // edges per CTA
#define NTH    256           // 8 warps: 2 m-groups x 4 n-groups, warp tile 32x64
#define NGROUP 8             // groups of 64 k (one full h_all row per edge)
#define BCHUNK_HALFS 8192    // 256 n * 32 k (per 32-k chunk)
#define AGROUP_BYTES 8192    // 64 m * 64 k * 2B
#define BGROUP_BYTES 32768   // 256 n * 64 k * 2B

// ---------------- smem layout (bytes) ----------------
#define SM_SIDX  0                 // 64 ints
#define SM_DIDX  256
#define SM_B1    512               // 256 f each
#define SM_G     1536
#define SM_BE    2560
#define SM_W3    3584
#define SM_SSUM  4608              // [4][64] f
#define SM_SSQ   5632
#define SM_SDOT  6656
#define SM_MUS   7680              // 64 f
#define SM_RSS   7936
#define SM_ABUF  8192              // 2 x 8KB
#define SM_BBUF  (SM_ABUF + 2 * AGROUP_BYTES)   // 2 x 32KB
#define SMEM_TOTAL (SM_BBUF + 2 * BGROUP_BYTES) // 90112 -> 2 CTAs/SM

// W1 pre-packed per-chunk into m16n8k16 fp16 B-fragment order (same as R7).
__device__ __half g_Bpack[2 * NGROUP * BCHUNK_HALFS];   // 256 KB

// ---------------- helpers ----------------
__device__ __forceinline__ uint32_t smem_u32(const void* p) {
    uint32_t a;
    asm("{ .reg .u64 t; cvta.to.shared.u64 t, %1; cvt.u32.u64 %0, t; }" : "=r"(a) : "l"(p));
    return a;
}
__device__ __forceinline__ float tanh_fast(float x) {
    float r;
    asm("tanh.approx.f32 %0, %1;" : "=f"(r) : "f"(x));
    return r;
}
__device__ __forceinline__ void cp16(uint32_t dst, const void* src) {
    asm volatile("cp.async.ca.shared.global [%0], [%1], 16;" :: "r"(dst), "l"(src));
}
__device__ __forceinline__ void cp_commit() {
    asm volatile("cp.async.commit_group;" ::: "memory");
}
template <int N>
__device__ __forceinline__ void cp_wait() {
    asm volatile("cp.async.wait_group %0;" :: "n"(N) : "memory");
}
__device__ __forceinline__ void mma_f16(float* c, const uint4& a, const uint2& b) {
    asm volatile(
        "mma.sync.aligned.m16n8k16.row.col.f32.f16.f16.f32 "
        "{%0,%1,%2,%3}, {%4,%5,%6,%7}, {%8,%9}, {%0,%1,%2,%3};"
        : "+f"(c[0]), "+f"(c[1]), "+f"(c[2]), "+f"(c[3])
        : "r"(a.x), "r"(a.y), "r"(a.z), "r"(a.w), "r"(b.x), "r"(b.y));
}

// ---------------- W1 prep (identical layout to R7) ----------------
__global__ void prep_w1(const float* __restrict__ W1) {
    int i = blockIdx.x * blockDim.x + threadIdx.x;
    if (i >= HIDN * KDIM) return;
    int n = i >> 9;
    int k = i & 511;
    int c = k >> 5, kc = k & 31;
    int kt = kc >> 4, kk = kc & 15;
    int g = ((n >> 6) << 3) | ((n >> 3) & 7);
    int lane = ((n & 7) << 2) | ((kk >> 1) & 3);
    int breg = kk >> 3, lo = kk & 1;
    int idx = c * BCHUNK_HALFS + ((g * 2 + kt) * 32 + lane) * 4 + breg * 2 + lo;
    g_Bpack[idx] = __float2half(W1[i]);
}

// ---------------- fused kernel ----------------
__global__ __launch_bounds__(NTH, 2)
void fused_edge_mlp_f16(const float* __restrict__ h_all,
                        const int*   __restrict__ src,
                        const int*   __restrict__ dst,
                        const float* __restrict__ b1,
                        const float* __restrict__ W3,
                        const float* __restrict__ b3,
                        const float* __restrict__ gamma2,
                        const float* __restrict__ beta2,
                        float* __restrict__ out,
                        int E) {
    extern __shared__ char smem[];
    const uint32_t sb = smem_u32(smem);

    const int tid  = threadIdx.x;
    const int wid  = tid >> 5;
    const int lane = tid & 31;
    const int mg   = wid >> 2;      // m-group (0..1)
    const int ng   = wid & 3;       // n-group (0..3)
    const int e_base = blockIdx.x * TILE_E;

    int*   sidx = (int*)(smem + SM_SIDX);
    int*   didx = (int*)(smem + SM_DIDX);
    float* b1s  = (float*)(smem + SM_B1);
    float* gs   = (float*)(smem + SM_G);
    float* bes  = (float*)(smem + SM_BE);
    float* w3s  = (float*)(smem + SM_W3);
    float* ssum = (float*)(smem + SM_SSUM);
    float* ssq  = (float*)(smem + SM_SSQ);
    float* sdot = (float*)(smem + SM_SDOT);
    float* mus  = (float*)(smem + SM_MUS);
    float* rss  = (float*)(smem + SM_RSS);

    // issue B group 0 immediately (no smem dependencies)
    {
        const __half* bsrc = g_Bpack;
        #pragma unroll
        for (int i = 0; i < 8; ++i)
            cp16(sb + SM_BBUF + (i * NTH + tid) * 16, bsrc + (i * NTH + tid) * 8);
        cp_commit();
    }

    if (tid < TILE_E) {
        int eg = e_base + tid;
        if (eg >= E) eg = E - 1;
        sidx[tid] = src[eg];
        didx[tid] = dst[eg];
    }
    if (tid < HIDN) {
        b1s[tid] = b1[tid];
        gs[tid]  = gamma2[tid];
        bes[tid] = beta2[tid];
        w3s[tid] = W3[tid];
    }
    __syncthreads();

    // ---- per-lane invariant addressing ----
    // gather: lane reads rows e_j = j*16 + t4 at float4 column q (k = 4q..4q+3)
    const int t4 = tid >> 4;        // row-within-16 (= fragment r)
    const int q  = tid & 15;        // float4 column within 64-float row
    // STS fragment offsets (bytes, within group A buffer): addr = j*1024 + o_p
    int o_p[2];
    {
        const int cc = q >> 3;                 // chunk within group
        #pragma unroll
        for (int p = 0; p < 2; ++p) {
            int kcp = (q & 7) * 4 + 2 * p;
            int kt = kcp >> 4, kk = kcp & 15;
            int ln = ((t4 & 7) << 2) | ((kk >> 1) & 3);
            int areg = (t4 >> 3) | ((kk >> 3) << 1);
            o_p[p] = cc * 4096 + (kt * 32 + ln) * 16 + areg * 4;
        }
    }

    float acc[2][8][4];
    #pragma unroll
    for (int mt = 0; mt < 2; ++mt)
        #pragma unroll
        for (int nt = 0; nt < 8; ++nt)
            #pragma unroll
            for (int j = 0; j < 4; ++j) acc[mt][nt][j] = 0.f;

    // gather + convert group 0 (l=0, src)
    uint32_t ph[4][2];              // [j][p] half2 pairs
    {
        #pragma unroll
        for (int j = 0; j < 4; ++j) {
            int nidx = sidx[j * 16 + t4];
            float4 v = *(const float4*)(h_all + (size_t)nidx * DHEAD + q * 4);
            __half2 a = __floats2half2_rn(tanh_fast(v.x * 0.1f), tanh_fast(v.y * 0.1f));
            __half2 b = __floats2half2_rn(tanh_fast(v.z * 0.1f), tanh_fast(v.w * 0.1f));
            ph[j][0] = *(uint32_t*)&a;
            ph[j][1] = *(uint32_t*)&b;
        }
    }
    // STS group 0 into A buf 0
    #pragma unroll
    for (int j = 0; j < 4; ++j) {
        *(uint32_t*)(smem + SM_ABUF + j * 1024 + o_p[0]) = ph[j][0];
        *(uint32_t*)(smem + SM_ABUF + j * 1024 + o_p[1]) = ph[j][1];
    }
    // gather + convert group 1 (l=0, dst)
    {
        #pragma unroll
        for (int j = 0; j < 4; ++j) {
            int nidx = didx[j * 16 + t4];
            float4 v = *(const float4*)(h_all + (size_t)nidx * DHEAD + q * 4);
            __half2 a = __floats2half2_rn(tanh_fast(v.x * 0.1f), tanh_fast(v.y * 0.1f));
            __half2 b = __floats2half2_rn(tanh_fast(v.z * 0.1f), tanh_fast(v.w * 0.1f));
            ph[j][0] = *(uint32_t*)&a;
            ph[j][1] = *(uint32_t*)&b;
        }
    }

    #pragma unroll 1
    for (int g = 0; g < NGROUP; ++g) {
        cp_wait<0>();
        __syncthreads();   // B(g) + A(g) visible; old buffers free

        // issue B(g+1) into the other slot
        if (g < NGROUP - 1) {
            const __half* bsrc = g_Bpack + (size_t)(g + 1) * 2 * BCHUNK_HALFS;
            uint32_t bdst = sb + SM_BBUF + ((g + 1) & 1) * BGROUP_BYTES;
            #pragma unroll
            for (int i = 0; i < 8; ++i)
                cp16(bdst + (i * NTH + tid) * 16, bsrc + (i * NTH + tid) * 8);
            cp_commit();
        }

        // STS A(g+1) from ph
        if (g < NGROUP - 1) {
            char* ab = smem + SM_ABUF + ((g + 1) & 1) * AGROUP_BYTES;
            #pragma unroll
            for (int j = 0; j < 4; ++j) {
                *(uint32_t*)(ab + j * 1024 + o_p[0]) = ph[j][0];
                *(uint32_t*)(ab + j * 1024 + o_p[1]) = ph[j][1];
            }
        }

        // gather + convert A(g+2) -> ph (hidden under MMA)
        if (g < NGROUP - 2) {
            const int gn = g + 2;
            const int l = gn >> 1;
            const float im = 0.1f * (float)(l + 1);
            const int* ip = (gn & 1) ? didx : sidx;
            const float* hb = h_all + (size_t)l * (NNODES * DHEAD);
            #pragma unroll
            for (int j = 0; j < 4; ++j) {
                int nidx = ip[j * 16 + t4];
                float4 v = *(const float4*)(hb + (size_t)nidx * DHEAD + q * 4);
                __half2 a = __floats2half2_rn(tanh_fast(v.x * im), tanh_fast(v.y * im));
                __half2 b = __floats2half2_rn(tanh_fast(v.z * im), tanh_fast(v.w * im));
                ph[j][0] = *(uint32_t*)&a;
                ph[j][1] = *(uint32_t*)&b;
            }
        }

        // ---- MMA on group g: 4 kt-steps (2 chunks x 2 kt) ----
        {
            const char* Ag = smem + SM_ABUF + (g & 1) * AGROUP_BYTES;
            const char* Bg = smem + SM_BBUF + (g & 1) * BGROUP_BYTES;
            #pragma unroll
            for (int ktc = 0; ktc < 4; ++ktc) {
                const int chunk = ktc >> 1, kt = ktc & 1;
                const char* Ab = Ag + chunk * 4096;
                const char* Bb = Bg + chunk * 16384;
                uint2 bb[8];
                #pragma unroll
                for (int nt = 0; nt < 8; ++nt)
                    bb[nt] = *(const uint2*)(Bb + (((ng * 8 + nt) * 2 + kt) * 32 + lane) * 8);
                uint4 aa[2];
                #pragma unroll
                for (int mt = 0; mt < 2; ++mt)
                    aa[mt] = *(const uint4*)(Ab + (((mg * 2 + mt) * 2 + kt) * 32 + lane) * 16);
                #pragma unroll
                for (int mt = 0; mt < 2; ++mt)
                    #pragma unroll
                    for (int nt = 0; nt < 8; ++nt)
                        mma_f16(acc[mt][nt], aa[mt], bb[nt]);
            }
        }
    }

    // ---------------- epilogue ----------------
    const int qr = lane >> 2;
    const int ql = lane & 3;

    float sums[2][2] = {{0.f, 0.f}, {0.f, 0.f}};
    float sqs[2][2]  = {{0.f, 0.f}, {0.f, 0.f}};
    #pragma unroll
    for (int mt = 0; mt < 2; ++mt) {
        #pragma unroll
        for (int nt = 0; nt < 8; ++nt) {
            int colb = ng * 64 + nt * 8 + ql * 2;
            float b10 = b1s[colb], b11 = b1s[colb + 1];
            float v0 = acc[mt][nt][0] + b10;
            float v1 = acc[mt][nt][1] + b11;
            float v2 = acc[mt][nt][2] + b10;
            float v3 = acc[mt][nt][3] + b11;
            acc[mt][nt][0] = v0; acc[mt][nt][1] = v1;
            acc[mt][nt][2] = v2; acc[mt][nt][3] = v3;
            sums[mt][0] += v0 + v1;           sums[mt][1] += v2 + v3;
            sqs[mt][0] = fmaf(v0, v0, sqs[mt][0]); sqs[mt][0] = fmaf(v1, v1, sqs[mt][0]);
            sqs[mt][1] = fmaf(v2, v2, sqs[mt][1]); sqs[mt][1] = fmaf(v3, v3, sqs[mt][1]);
        }
    }
    #pragma unroll
    for (int off = 1; off <= 2; off <<= 1) {
        #pragma unroll
        for (int mt = 0; mt < 2; ++mt)
            #pragma unroll
            for (int ro = 0; ro < 2; ++ro) {
                sums[mt][ro] += __shfl_xor_sync(0xffffffffu, sums[mt][ro], off);
                sqs[mt][ro]  += __shfl_xor_sync(0xffffffffu, sqs[mt][ro], off);
            }
    }
    if (ql == 0) {
        #pragma unroll
        for (int mt = 0; mt < 2; ++mt)
            #pragma unroll
            for (int ro = 0; ro < 2; ++ro) {
                int row = mg * 32 + mt * 16 + ro * 8 + qr;
                ssum[ng * 64 + row] = sums[mt][ro];
                ssq[ng * 64 + row]  = sqs[mt][ro];
            }
    }
    __syncthreads();

    if (tid < TILE_E) {
        float ts = ssum[tid] + ssum[64 + tid] + ssum[128 + tid] + ssum[192 + tid];
        float tq = ssq[tid]  + ssq[64 + tid]  + ssq[128 + tid]  + ssq[192 + tid];
        float mu  = ts * (1.f / 256.f);
        float var = tq * (1.f / 256.f) - mu * mu;
        mus[tid] = mu;
        rss[tid] = rsqrtf(var + 1e-5f);
    }
    __syncthreads();

    float dots[2][2] = {{0.f, 0.f}, {0.f, 0.f}};
    #pragma unroll
    for (int mt = 0; mt < 2; ++mt) {
        int row0 = mg * 32 + mt * 16 + qr;
        float mu0 = mus[row0],     rs0 = rss[row0];
        float mu1 = mus[row0 + 8], rs1 = rss[row0 + 8];
        #pragma unroll
        for (int nt = 0; nt < 8; ++nt) {
            int colb = ng * 64 + nt * 8 + ql * 2;
            float g0 = gs[colb], g1 = gs[colb + 1];
            float e0 = bes[colb], e1 = bes[colb + 1];
            float w0 = w3s[colb], w1 = w3s[colb + 1];
            float y;
            y = fmaxf((acc[mt][nt][0] - mu0) * rs0 * g0 + e0, 0.f); dots[mt][0] = fmaf(y, w0, dots[mt][0]);
            y = fmaxf((acc[mt][nt][1] - mu0) * rs0 * g1 + e1, 0.f); dots[mt][0] = fmaf(y, w1, dots[mt][0]);
            y = fmaxf((acc[mt][nt][2] - mu1) * rs1 * g0 + e0, 0.f); dots[mt][1] = fmaf(y, w0, dots[mt][1]);
            y = fmaxf((acc[mt][nt][3] - mu1) * rs1 * g1 + e1, 0.f); dots[mt][1] = fmaf(y, w1, dots[mt][1]);
        }
    }
    #pragma unroll
    for (int off = 1; off <= 2; off <<= 1)
        #pragma unroll
        for (int mt = 0; mt < 2; ++mt)
            #pragma unroll
            for (int ro = 0; ro < 2; ++ro)
                dots[mt][ro] += __shfl_xor_sync(0xffffffffu, dots[mt][ro], off);
    if (ql == 0) {
        #pragma unroll
        for (int mt = 0; mt < 2; ++mt)
            #pragma unroll
            for (int ro = 0; ro < 2; ++ro) {
                int row = mg * 32 + mt * 16 + ro * 8 + qr;
                sdot[ng * 64 + row] = dots[mt][ro];
            }
    }
    __syncthreads();

    if (tid < TILE_E) {
        int eg = e_base + tid;
        if (eg < E) {
            out[eg] = sdot[tid] + sdot[64 + tid] + sdot[128 + tid] + sdot[192 + tid] + b3[0];
        }
    }
}

extern "C" void kernel_launch(void* const* d_in, const int* in_sizes, int n_in,
                              void* d_out, int out_size) {
    const float* h_all  = (const float*)d_in[0];
    const int*   src    = (const int*)  d_in[1];
    const int*   dst    = (const int*)  d_in[2];
    const float* W1     = (const float*)d_in[3];
    const float* b1     = (const float*)d_in[4];
    const float* W3     = (const float*)d_in[5];
    const float* b3     = (const float*)d_in[6];
    const float* gamma2 = (const float*)d_in[7];
    const float* beta2  = (const float*)d_in[8];
    float* out = (float*)d_out;

    const int E = in_sizes[1];

    cudaFuncSetAttribute(fused_edge_mlp_f16,
                         cudaFuncAttributeMaxDynamicSharedMemorySize, SMEM_TOTAL);

    prep_w1<<<(HIDN * KDIM + 255) / 256, 256>>>(W1);

    int nb = (E + TILE_E - 1) / TILE_E;
    fused_edge_mlp_f16<<<nb, NTH, SMEM_TOTAL>>>(
        h_all, src, dst, b1, W3, b3, gamma2, beta2, out, E);
}